// round 1
// baseline (speedup 1.0000x reference)
#include <cuda_runtime.h>
#include <math.h>

#define V 10000
#define D 300
#define B 64
#define L 128
#define QS 10240          // q row stride (40*256, padded, zeroed)
#define VC1 2048          // Z-pass v-chunk
#define VC2 2048          // q-pass v-chunk
#define VT3 256           // gemm v-tile
#define DT3 32            // gemm d-tile

__device__ float  g_context[D];
__device__ float  g_cn;
__device__ float2 g_AB[V];
__device__ float  g_Z[V];
__device__ int    g_used[V];
__device__ float  g_q[(size_t)B * QS];

// ---------------------------------------------------------------- mark used
__global__ void k_mark(const int* __restrict__ cl, const int* __restrict__ len) {
    int i = blockIdx.x * blockDim.x + threadIdx.x;
    if (i >= B * L) return;
    int b = i / L, l = i % L;
    if (l < len[b]) g_used[cl[i]] = 1;
}

// -------------------------------------------------- context (ragged mean of means)
__global__ void k_context(const int* __restrict__ cl, const int* __restrict__ len,
                          const float* __restrict__ ew) {
    __shared__ int sc[L];
    int b = blockIdx.x;
    int n = len[b];
    for (int l = threadIdx.x; l < n; l += blockDim.x) sc[l] = cl[b * L + l];
    __syncthreads();
    int d = threadIdx.x;
    if (d >= D) return;
    float acc = 0.f;
    for (int l = 0; l < n; l++) acc += ew[(size_t)sc[l] * D + d];
    float denom = (float)(n > 1 ? n : 1);
    atomicAdd(&g_context[d], acc / (denom * (float)B));
}

// ---------------------------------------------------------------- ||context||
__global__ void k_cnorm() {
    __shared__ float red[32];
    int t = threadIdx.x;
    float v = (t < D) ? g_context[t] : 0.f;
    float s = v * v;
    for (int o = 16; o; o >>= 1) s += __shfl_down_sync(0xFFFFFFFFu, s, o);
    if ((t & 31) == 0) red[t >> 5] = s;
    __syncthreads();
    if (t < 32) {
        int nw = blockDim.x >> 5;
        float x = (t < nw) ? red[t] : 0.f;
        for (int o = 16; o; o >>= 1) x += __shfl_down_sync(0xFFFFFFFFu, x, o);
        if (t == 0) g_cn = sqrtf(x);
    }
}

// ----------------------------------- cos[v] and fused coefficients A,B (warp per v)
__global__ void k_cos(const float* __restrict__ cw, const float* __restrict__ aff,
                      const float* __restrict__ lam) {
    __shared__ float sctx[D];
    for (int i = threadIdx.x; i < D; i += blockDim.x) sctx[i] = g_context[i];
    __syncthreads();
    int w = threadIdx.x >> 5, lane = threadIdx.x & 31;
    int v = blockIdx.x * 8 + w;
    if (v >= V) return;
    const float* row = cw + (size_t)v * D;
    float dot = 0.f, nn = 0.f;
    for (int i = lane; i < D; i += 32) {
        float x = row[i];
        dot += x * sctx[i];
        nn  += x * x;
    }
    for (int o = 16; o; o >>= 1) {
        dot += __shfl_down_sync(0xFFFFFFFFu, dot, o);
        nn  += __shfl_down_sync(0xFFFFFFFFu, nn, o);
    }
    if (lane == 0) {
        float c = fabsf(dot) / fmaxf(g_cn * sqrtf(nn), 1e-8f);
        float la = lam[v], af = aff[v];
        g_AB[v] = make_float2(5.f * la * c, 5.f * (1.f - la) * af);
    }
}

// --------------------------------------- Z-pass: sum_v exp(5w) per used concept row
__global__ void k_Z(const float* __restrict__ em) {
    __shared__ float2 sAB[VC1];
    int v0 = blockIdx.x * VC1;
    int nv = min(VC1, V - v0);
    for (int i = threadIdx.x; i < nv; i += blockDim.x) sAB[i] = g_AB[v0 + i];
    __syncthreads();
    int r0 = blockIdx.y * 200;
    int r1 = min(r0 + 200, V);
    int lane = threadIdx.x & 31;
    for (int r = r0; r < r1; r++) {
        if (!g_used[r]) continue;
        const float* row = em + (size_t)r * V + v0;
        float acc = 0.f;
        for (int i = threadIdx.x; i < nv; i += blockDim.x) {
            float e = row[i];
            float2 ab = sAB[i];
            float bb = (e > 0.f) ? ab.y : 0.f;
            acc += __expf(fmaf(e, ab.x, bb));
        }
        for (int o = 16; o; o >>= 1) acc += __shfl_down_sync(0xFFFFFFFFu, acc, o);
        if (lane == 0) atomicAdd(&g_Z[r], acc);
    }
}

// ---------------- q-pass: q[b,v] = sum_{l<len} exp(5w(c_l,v)) / (Z[c_l]*denom_b)
__global__ void k_q(const int* __restrict__ cl, const int* __restrict__ lenp,
                    const float* __restrict__ em) {
    __shared__ float2 sAB[VC2];
    __shared__ int   sc[L];
    __shared__ float ss[L];
    int b  = blockIdx.y;
    int v0 = blockIdx.x * VC2;
    int n  = lenp[b];
    int t  = threadIdx.x;
    for (int i = t; i < VC2; i += 256) {
        int v = v0 + i;
        sAB[i] = (v < V) ? g_AB[v] : make_float2(0.f, 0.f);
    }
    if (t < n) {
        int c = cl[b * L + t];
        sc[t] = c;
        float denom = (float)(n > 1 ? n : 1);
        ss[t] = 1.f / (g_Z[c] * denom);
    }
    __syncthreads();

    float acc[8];
#pragma unroll
    for (int j = 0; j < 8; j++) acc[j] = 0.f;

    for (int l = 0; l < n; l++) {
        const float* row = em + (size_t)sc[l] * V;
        float s = ss[l];
#pragma unroll
        for (int g = 0; g < 2; g++) {
            int vi = g * 1024 + t * 4;
            int v  = v0 + vi;
            float4 e4;
            if (v + 3 < V) {
                e4 = *reinterpret_cast<const float4*>(row + v);
            } else {
                e4.x = (v     < V) ? row[v]     : 0.f;
                e4.y = (v + 1 < V) ? row[v + 1] : 0.f;
                e4.z = (v + 2 < V) ? row[v + 2] : 0.f;
                e4.w = (v + 3 < V) ? row[v + 3] : 0.f;
            }
            float2 a0 = sAB[vi], a1 = sAB[vi + 1], a2 = sAB[vi + 2], a3 = sAB[vi + 3];
            acc[g*4+0] += __expf(fmaf(e4.x, a0.x, (e4.x > 0.f) ? a0.y : 0.f)) * s;
            acc[g*4+1] += __expf(fmaf(e4.y, a1.x, (e4.y > 0.f) ? a1.y : 0.f)) * s;
            acc[g*4+2] += __expf(fmaf(e4.z, a2.x, (e4.z > 0.f) ? a2.y : 0.f)) * s;
            acc[g*4+3] += __expf(fmaf(e4.w, a3.x, (e4.w > 0.f) ? a3.y : 0.f)) * s;
        }
    }

#pragma unroll
    for (int g = 0; g < 2; g++) {
        int v = v0 + g * 1024 + t * 4;
        if (v + 3 < V) {
            *reinterpret_cast<float4*>(&g_q[(size_t)b * QS + v]) =
                make_float4(acc[g*4+0], acc[g*4+1], acc[g*4+2], acc[g*4+3]);
        } else {
#pragma unroll
            for (int j = 0; j < 4; j++)
                if (v + j < V) g_q[(size_t)b * QS + v + j] = acc[g*4+j];
        }
    }
}

// ---------------------------------------------- out = q @ W  (smem-tiled, atomics)
__global__ void k_out(const float* __restrict__ cw, float* __restrict__ out) {
    __shared__ float qt[32][68];   // [vv][b], pad 68 -> 16B-aligned rows
    __shared__ float wt[32][34];   // [vv][d], pad 34 -> 8B-aligned rows
    int t   = threadIdx.x;
    int va  = blockIdx.x * VT3;
    int d0  = blockIdx.y * DT3;
    int dl2 = t & 15;              // d pair index: d = d0 + dl2*2 + {0,1}
    int bq  = t >> 4;              // b quad index: b = bq*4 + {0..3}
    float acc[2][4];
#pragma unroll
    for (int i = 0; i < 2; i++)
#pragma unroll
        for (int j = 0; j < 4; j++) acc[i][j] = 0.f;

    for (int sub = 0; sub < VT3 / 32; sub++) {
        int vs = va + sub * 32;
        __syncthreads();
#pragma unroll
        for (int k = 0; k < 8; k++) {        // 64x32 q tile
            int i = k * 256 + t;
            int b = i >> 5, vv = i & 31;
            qt[vv][b] = g_q[(size_t)b * QS + vs + vv];  // pad region is zero
        }
#pragma unroll
        for (int k = 0; k < 4; k++) {        // 32x32 W tile
            int i = k * 256 + t;
            int vv = i >> 5, dl = i & 31;
            int v = vs + vv, d = d0 + dl;
            wt[vv][dl] = (v < V && d < D) ? cw[(size_t)v * D + d] : 0.f;
        }
        __syncthreads();
#pragma unroll
        for (int vv = 0; vv < 32; vv++) {
            float4 q4 = *reinterpret_cast<const float4*>(&qt[vv][bq * 4]);
            float2 w2 = *reinterpret_cast<const float2*>(&wt[vv][dl2 * 2]);
            acc[0][0] += q4.x * w2.x;  acc[1][0] += q4.x * w2.y;
            acc[0][1] += q4.y * w2.x;  acc[1][1] += q4.y * w2.y;
            acc[0][2] += q4.z * w2.x;  acc[1][2] += q4.z * w2.y;
            acc[0][3] += q4.w * w2.x;  acc[1][3] += q4.w * w2.y;
        }
    }
#pragma unroll
    for (int dj = 0; dj < 2; dj++) {
        int d = d0 + dl2 * 2 + dj;
        if (d < D) {
#pragma unroll
            for (int bj = 0; bj < 4; bj++) {
                int b = bq * 4 + bj;
                atomicAdd(&out[b * D + d], acc[dj][bj]);
            }
        }
    }
}

// ================================================================= launch
extern "C" void kernel_launch(void* const* d_in, const int* in_sizes, int n_in,
                              void* d_out, int out_size) {
    const int*   cl  = (const int*)d_in[0];
    const int*   len = (const int*)d_in[1];
    const float* ew  = (const float*)d_in[2];
    const float* cw  = (const float*)d_in[3];
    const float* em  = (const float*)d_in[4];
    const float* aff = (const float*)d_in[5];
    const float* lam = (const float*)d_in[6];
    float* out = (float*)d_out;

    void* p;
    cudaGetSymbolAddress(&p, g_context); cudaMemsetAsync(p, 0, D * sizeof(float));
    cudaGetSymbolAddress(&p, g_used);    cudaMemsetAsync(p, 0, V * sizeof(int));
    cudaGetSymbolAddress(&p, g_Z);       cudaMemsetAsync(p, 0, V * sizeof(float));
    cudaGetSymbolAddress(&p, g_q);       cudaMemsetAsync(p, 0, (size_t)B * QS * sizeof(float));
    cudaMemsetAsync(d_out, 0, (size_t)out_size * sizeof(float));

    k_mark<<<(B * L + 255) / 256, 256>>>(cl, len);
    k_context<<<B, 320>>>(cl, len, ew);
    k_cnorm<<<1, 320>>>();
    k_cos<<<(V + 7) / 8, 256>>>(cw, aff, lam);
    { dim3 g(5, 50);  k_Z<<<g, 256>>>(em); }
    { dim3 g(5, B);   k_q<<<g, 256>>>(cl, len, em); }
    { dim3 g((V + VT3 - 1) / VT3, (D + DT3 - 1) / DT3); k_out<<<g, 256>>>(cw, out); }
}

// round 3
// speedup vs baseline: 2.8000x; 2.8000x over previous
#include <cuda_runtime.h>
#include <math.h>

#define V 10000
#define D 300
#define B 64
#define L 128
#define QS 10240          // q row stride (padded)
#define VC1 2048          // Z-pass v-chunk (5 chunks)
#define NC1 5
#define RZ 16             // rows per Z block
#define VC2 1024          // q-pass v-chunk (10 chunks)
#define NC2 10
#define VT3 256           // gemm v-tile
#define DT3 32            // gemm d-tile

__device__ float  g_context[D];
__device__ float  g_cn;
__device__ float2 g_AB[V];
__device__ float  g_Z[V];
__device__ int    g_used[V];
__device__ int    g_list[B * L];
__device__ int    g_cnt;
__device__ float  g_q[(size_t)B * QS];

// ---------------- context (ragged mean of means) + mark/compact used concepts
__global__ void k_context(const int* __restrict__ cl, const int* __restrict__ len,
                          const float* __restrict__ ew) {
    __shared__ int sc[32];
    int b = blockIdx.x, part = blockIdx.y;
    int n = len[b];
    int t = threadIdx.x;

    // mark + compact (part 0 only; blockDim >= L)
    if (part == 0 && t < n) {
        int c = cl[b * L + t];
        if (atomicExch(&g_used[c], 1) == 0) {
            int k = atomicAdd(&g_cnt, 1);
            g_list[k] = c;
        }
    }

    int l0 = part * 32;
    int l1 = min(n, l0 + 32);
    int cnt = l1 - l0;
    if (t < cnt) sc[t] = cl[b * L + l0 + t];
    __syncthreads();
    if (t >= D || cnt <= 0) return;
    float acc = 0.f;
    for (int i = 0; i < cnt; i++) acc += ew[(size_t)sc[i] * D + t];
    float denom = (float)(n > 1 ? n : 1);
    atomicAdd(&g_context[t], acc / (denom * (float)B));
}

// ---------------------------------------------------------------- ||context||
__global__ void k_cnorm() {
    __shared__ float red[32];
    int t = threadIdx.x;
    float v = (t < D) ? g_context[t] : 0.f;
    float s = v * v;
    for (int o = 16; o; o >>= 1) s += __shfl_down_sync(0xFFFFFFFFu, s, o);
    if ((t & 31) == 0) red[t >> 5] = s;
    __syncthreads();
    if (t < 32) {
        int nw = blockDim.x >> 5;
        float x = (t < nw) ? red[t] : 0.f;
        for (int o = 16; o; o >>= 1) x += __shfl_down_sync(0xFFFFFFFFu, x, o);
        if (t == 0) g_cn = sqrtf(x);
    }
}

// ------------------------- cos[v] -> fused coeffs A,B  (warp per row, float4)
__global__ void k_cos(const float* __restrict__ cw, const float* __restrict__ aff,
                      const float* __restrict__ lam) {
    __shared__ float sctx[304];
    for (int i = threadIdx.x; i < D; i += blockDim.x) sctx[i] = g_context[i];
    __syncthreads();
    int w = threadIdx.x >> 5, lane = threadIdx.x & 31;
    int v = blockIdx.x * 8 + w;
    if (v >= V) return;
    const float4* row = reinterpret_cast<const float4*>(cw + (size_t)v * D);
    const float4* ctx4 = reinterpret_cast<const float4*>(sctx);
    float dot = 0.f, nn = 0.f;
#pragma unroll
    for (int k = 0; k < 3; k++) {
        int i = lane + k * 32;
        if (i < D / 4) {
            float4 x = row[i], c = ctx4[i];
            dot += x.x * c.x + x.y * c.y + x.z * c.z + x.w * c.w;
            nn  += x.x * x.x + x.y * x.y + x.z * x.z + x.w * x.w;
        }
    }
    for (int o = 16; o; o >>= 1) {
        dot += __shfl_down_sync(0xFFFFFFFFu, dot, o);
        nn  += __shfl_down_sync(0xFFFFFFFFu, nn, o);
    }
    if (lane == 0) {
        float c = fabsf(dot) / fmaxf(g_cn * sqrtf(nn), 1e-8f);
        float la = lam[v], af = aff[v];
        g_AB[v] = make_float2(5.f * la * c, 5.f * (1.f - la) * af);
    }
}

// ------------- Z-pass: per used row r, Z[r] += sum_v exp(A_v*e + B_v*(e>0))
__global__ void k_Z(const float* __restrict__ em) {
    int cnt = g_cnt;
    int r0 = blockIdx.y * RZ;
    if (r0 >= cnt) return;
    __shared__ float2 sAB[VC1];
    int v0 = blockIdx.x * VC1;
    int nv = min(VC1, V - v0);          // 2048 or 1808, both %4==0
    int nv4 = nv >> 2;
    for (int i = threadIdx.x; i < nv; i += blockDim.x) sAB[i] = g_AB[v0 + i];
    __syncthreads();
    int r1 = min(r0 + RZ, cnt);
    int t = threadIdx.x, lane = t & 31;
    for (int ri = r0; ri < r1; ri++) {
        int r = g_list[ri];
        const float4* row = reinterpret_cast<const float4*>(em + (size_t)r * V + v0);
        float acc = 0.f;
#pragma unroll 2
        for (int i4 = t; i4 < nv4; i4 += 256) {
            float4 e = row[i4];
            float2 a0 = sAB[i4*4], a1 = sAB[i4*4+1], a2 = sAB[i4*4+2], a3 = sAB[i4*4+3];
            acc += __expf(fmaf(e.x, a0.x, (e.x > 0.f) ? a0.y : 0.f));
            acc += __expf(fmaf(e.y, a1.x, (e.y > 0.f) ? a1.y : 0.f));
            acc += __expf(fmaf(e.z, a2.x, (e.z > 0.f) ? a2.y : 0.f));
            acc += __expf(fmaf(e.w, a3.x, (e.w > 0.f) ? a3.y : 0.f));
        }
        for (int o = 16; o; o >>= 1) acc += __shfl_down_sync(0xFFFFFFFFu, acc, o);
        if (lane == 0) atomicAdd(&g_Z[r], acc);
    }
}

// ---- q-pass: q[b,v] = sum_l exp(w(c_l,v))/(Z[c_l]*denom_b); double-buffered
__global__ void k_q(const int* __restrict__ cl, const int* __restrict__ lenp,
                    const float* __restrict__ em) {
    __shared__ int   sc[L];
    __shared__ float ss[L];
    int b  = blockIdx.y;
    int v0 = blockIdx.x * VC2;
    int n  = lenp[b];
    int t  = threadIdx.x;
    if (t < n) {
        int c = cl[b * L + t];
        sc[t] = c;
        float denom = (float)(n > 1 ? n : 1);
        ss[t] = 1.f / (g_Z[c] * denom);
    }
    __syncthreads();

    int v = v0 + t * 4;               // multiple of 4; V%4==0 so float4 safe iff v<V
    bool vok = (v < V);
    float2 a0, a1, a2, a3;
    if (vok) {
        a0 = g_AB[v]; a1 = g_AB[v + 1]; a2 = g_AB[v + 2]; a3 = g_AB[v + 3];
    } else {
        a0 = a1 = a2 = a3 = make_float2(0.f, 0.f);
    }

    float acc0 = 0.f, acc1 = 0.f, acc2 = 0.f, acc3 = 0.f;
    if (n > 0 && vok) {
        float4 e4 = *reinterpret_cast<const float4*>(em + (size_t)sc[0] * V + v);
        for (int l = 0; l < n; l++) {
            float4 cur = e4;
            if (l + 1 < n)
                e4 = *reinterpret_cast<const float4*>(em + (size_t)sc[l + 1] * V + v);
            float s = ss[l];
            acc0 = fmaf(__expf(fmaf(cur.x, a0.x, (cur.x > 0.f) ? a0.y : 0.f)), s, acc0);
            acc1 = fmaf(__expf(fmaf(cur.y, a1.x, (cur.y > 0.f) ? a1.y : 0.f)), s, acc1);
            acc2 = fmaf(__expf(fmaf(cur.z, a2.x, (cur.z > 0.f) ? a2.y : 0.f)), s, acc2);
            acc3 = fmaf(__expf(fmaf(cur.w, a3.x, (cur.w > 0.f) ? a3.y : 0.f)), s, acc3);
        }
    }
    // unconditional store covers padding [V, QS) with zeros (no memset needed)
    *reinterpret_cast<float4*>(&g_q[(size_t)b * QS + v]) = make_float4(acc0, acc1, acc2, acc3);
}

// ---------------------------------------------- out = q @ W  (smem-tiled, atomics)
__global__ void k_out(const float* __restrict__ cw, float* __restrict__ out) {
    __shared__ float qt[32][68];
    __shared__ float wt[32][34];
    int t   = threadIdx.x;
    int va  = blockIdx.x * VT3;
    int d0  = blockIdx.y * DT3;
    int dl2 = t & 15;
    int bq  = t >> 4;
    float acc[2][4];
#pragma unroll
    for (int i = 0; i < 2; i++)
#pragma unroll
        for (int j = 0; j < 4; j++) acc[i][j] = 0.f;

    for (int sub = 0; sub < VT3 / 32; sub++) {
        int vs = va + sub * 32;
        __syncthreads();
#pragma unroll
        for (int k = 0; k < 8; k++) {
            int i = k * 256 + t;
            int b = i >> 5, vv = i & 31;
            qt[vv][b] = g_q[(size_t)b * QS + vs + vv];
        }
#pragma unroll
        for (int k = 0; k < 4; k++) {
            int i = k * 256 + t;
            int vv = i >> 5, dl = i & 31;
            int v = vs + vv, d = d0 + dl;
            wt[vv][dl] = (v < V && d < D) ? cw[(size_t)v * D + d] : 0.f;
        }
        __syncthreads();
#pragma unroll
        for (int vv = 0; vv < 32; vv++) {
            float4 q4 = *reinterpret_cast<const float4*>(&qt[vv][bq * 4]);
            float2 w2 = *reinterpret_cast<const float2*>(&wt[vv][dl2 * 2]);
            acc[0][0] += q4.x * w2.x;  acc[1][0] += q4.x * w2.y;
            acc[0][1] += q4.y * w2.x;  acc[1][1] += q4.y * w2.y;
            acc[0][2] += q4.z * w2.x;  acc[1][2] += q4.z * w2.y;
            acc[0][3] += q4.w * w2.x;  acc[1][3] += q4.w * w2.y;
        }
    }
#pragma unroll
    for (int dj = 0; dj < 2; dj++) {
        int d = d0 + dl2 * 2 + dj;
        if (d < D) {
#pragma unroll
            for (int bj = 0; bj < 4; bj++) {
                int b = bq * 4 + bj;
                atomicAdd(&out[b * D + d], acc[dj][bj]);
            }
        }
    }
}

// ================================================================= launch
extern "C" void kernel_launch(void* const* d_in, const int* in_sizes, int n_in,
                              void* d_out, int out_size) {
    const int*   cl  = (const int*)d_in[0];
    const int*   len = (const int*)d_in[1];
    const float* ew  = (const float*)d_in[2];
    const float* cw  = (const float*)d_in[3];
    const float* em  = (const float*)d_in[4];
    const float* aff = (const float*)d_in[5];
    const float* lam = (const float*)d_in[6];
    float* out = (float*)d_out;

    void* p;
    cudaGetSymbolAddress(&p, g_context); cudaMemsetAsync(p, 0, D * sizeof(float));
    cudaGetSymbolAddress(&p, g_used);    cudaMemsetAsync(p, 0, V * sizeof(int));
    cudaGetSymbolAddress(&p, g_Z);       cudaMemsetAsync(p, 0, V * sizeof(float));
    cudaGetSymbolAddress(&p, g_cnt);     cudaMemsetAsync(p, 0, sizeof(int));
    cudaMemsetAsync(d_out, 0, (size_t)out_size * sizeof(float));

    { dim3 g(B, 4);          k_context<<<g, 320>>>(cl, len, ew); }
    k_cnorm<<<1, 320>>>();
    k_cos<<<(V + 7) / 8, 256>>>(cw, aff, lam);
    { dim3 g(NC1, 512);      k_Z<<<g, 256>>>(em); }          // 16 rows/block over compacted list
    { dim3 g(NC2, B);        k_q<<<g, 256>>>(cl, len, em); }
    { dim3 g((V + VT3 - 1) / VT3, (D + DT3 - 1) / DT3); k_out<<<g, 256>>>(cw, out); }
}